// round 1
// baseline (speedup 1.0000x reference)
#include <cuda_runtime.h>

// Bilateral filter, B=2 C=3 H=W=384, ksize=9, sigma=1.7.
// out = sum_t ws_t * exp(-(v_t-c)^2 * A) * v_t / sum_t ws_t * exp(...),
// A = 1/(2*sigma^2). All normalizations in the reference cancel.

#define TS   32          // output tile (square)
#define PX   4           // output rows per thread
#define BY   8           // threadIdx.y extent (BY*PX == TS)
#define HALO 4
#define SW   (TS + 2*HALO)   // 40
#define KS   9

__global__ __launch_bounds__(256)
void bilateral9_kernel(const float* __restrict__ x, float* __restrict__ out,
                       int H, int W) {
    __shared__ float sm[SW][SW];

    const int plane = blockIdx.z;
    const float* xp = x + (size_t)plane * H * W;
    float* op = out + (size_t)plane * H * W;
    const int x0 = blockIdx.x * TS;
    const int y0 = blockIdx.y * TS;
    const int tx = threadIdx.x;
    const int ty = threadIdx.y;
    const int tid = ty * 32 + tx;

    // ---- load 40x40 tile with reflect padding ----
    #pragma unroll
    for (int idx = tid; idx < SW * SW; idx += 256) {
        int ly = idx / SW, lx = idx - ly * SW;
        int gy = y0 + ly - HALO;
        int gx = x0 + lx - HALO;
        gy = gy < 0 ? -gy : (gy >= H ? 2 * H - 2 - gy : gy);
        gx = gx < 0 ? -gx : (gx >= W ? 2 * W - 2 - gx : gx);
        sm[ly][lx] = xp[(size_t)gy * W + gx];
    }
    __syncthreads();

    // sigma = 0.3*((9-1)/2 - 1) + 0.8 = 1.7 ;  A = 1/(2*sigma^2)
    const float A  = 1.0f / (2.0f * 1.7f * 1.7f);   // 0.173010...
    // exp(-A*u) ~= 1 + c1*u + c2*u^2 + c3*u^3 + c4*u^4,  u = diff^2 in [0,1]
    const float c1 = -A;
    const float c2 = 0.5f * A * A;
    const float c3 = -(A * A * A) * (1.0f / 6.0f);
    const float c4 = (A * A) * (A * A) * (1.0f / 24.0f);

    // exact 1D spatial gaussian (unnormalized): g[d] = exp(-A*d*d), d=0..4
    float g[5];
    #pragma unroll
    for (int d = 0; d < 5; d++) g[d] = expf(-A * (float)(d * d));

    // per-column spatial weights ws_x[j] = g[|j-4|]
    float wsx[KS];
    #pragma unroll
    for (int j = 0; j < KS; j++) wsx[j] = g[j < 4 ? 4 - j : j - 4];

    float c[PX], num[PX], den[PX];
    #pragma unroll
    for (int p = 0; p < PX; p++) {
        c[p] = sm[ty * PX + p + HALO][tx + HALO];
        num[p] = 0.0f;
        den[p] = 0.0f;
    }

    // rows spanned by the PX windows: r = 0 .. PX+8-1 (smem row ty*PX + r)
    #pragma unroll
    for (int r = 0; r < PX + KS - 1; r++) {
        float rn[PX], rd[PX];
        #pragma unroll
        for (int p = 0; p < PX; p++) { rn[p] = 0.0f; rd[p] = 0.0f; }

        #pragma unroll
        for (int j = 0; j < KS; j++) {
            float v = sm[ty * PX + r][tx + j];
            #pragma unroll
            for (int p = 0; p < PX; p++) {
                const int ky = r - p;
                if (ky >= 0 && ky < KS) {          // compile-time pruned
                    float d = v - c[p];
                    float u = d * d;
                    float e = fmaf(c4, u, c3);
                    e = fmaf(e, u, c2);
                    e = fmaf(e, u, c1);
                    e = fmaf(e, u, 1.0f);
                    float t = e * wsx[j];
                    rn[p] = fmaf(t, v, rn[p]);
                    rd[p] += t;
                }
            }
        }

        #pragma unroll
        for (int p = 0; p < PX; p++) {
            const int ky = r - p;
            if (ky >= 0 && ky < KS) {
                float gy = g[ky < 4 ? 4 - ky : ky - 4];
                num[p] = fmaf(gy, rn[p], num[p]);
                den[p] = fmaf(gy, rd[p], den[p]);
            }
        }
    }

    #pragma unroll
    for (int p = 0; p < PX; p++) {
        int oy = y0 + ty * PX + p;
        op[(size_t)oy * W + x0 + tx] = num[p] / den[p];
    }
}

extern "C" void kernel_launch(void* const* d_in, const int* in_sizes, int n_in,
                              void* d_out, int out_size) {
    const float* x = (const float*)d_in[0];
    float* out = (float*)d_out;
    const int H = 384, W = 384;
    const int planes = out_size / (H * W);   // B*C = 6

    dim3 block(32, BY, 1);
    dim3 grid(W / TS, H / TS, planes);
    bilateral9_kernel<<<grid, block>>>(x, out, H, W);
}

// round 2
// speedup vs baseline: 1.2481x; 1.2481x over previous
#include <cuda_runtime.h>

// Bilateral filter, B=2 C=3 H=W=384, ksize=9, sigma=1.7.
// out = sum_t ws_t * e(v_t) * v_t / sum_t ws_t * e(v_t),
// e(v) = exp(-(v-c)^2 * A), A = 1/(2*sigma^2). Reference normalizations cancel.
// Density exp replaced by degree-2 economized polynomial in u=(v-c)^2 in [0,1]
// (abs err <= ~6e-5). Column spatial weight folded into the poly coefficients.
// Two f32x2 lanes process 4 output rows per thread via packed FFMA2.

#define TS   32
#define PX   4
#define BY   8
#define HALO 4
#define SW   (TS + 2*HALO)   // 40
#define KS   9

typedef unsigned long long u64;

__device__ __forceinline__ u64 pack2(float lo, float hi) {
    u64 r; asm("mov.b64 %0, {%1,%2};" : "=l"(r) : "f"(lo), "f"(hi)); return r;
}
__device__ __forceinline__ void unpack2(u64 v, float& lo, float& hi) {
    asm("mov.b64 {%0,%1}, %2;" : "=f"(lo), "=f"(hi) : "l"(v));
}
__device__ __forceinline__ u64 fma2(u64 a, u64 b, u64 c) {
    u64 d; asm("fma.rn.f32x2 %0, %1, %2, %3;" : "=l"(d) : "l"(a), "l"(b), "l"(c)); return d;
}
__device__ __forceinline__ u64 add2(u64 a, u64 b) {
    u64 d; asm("add.rn.f32x2 %0, %1, %2;" : "=l"(d) : "l"(a), "l"(b)); return d;
}
__device__ __forceinline__ u64 mul2(u64 a, u64 b) {
    u64 d; asm("mul.rn.f32x2 %0, %1, %2;" : "=l"(d) : "l"(a), "l"(b)); return d;
}

// spatial weight for row offset ky (0..8), 0 if out of window
__device__ __forceinline__ float gw(const float* g, int ky) {
    return (ky >= 0 && ky < KS) ? g[ky < 4 ? 4 - ky : ky - 4] : 0.0f;
}

__global__ __launch_bounds__(256)
void bilateral9_kernel(const float* __restrict__ x, float* __restrict__ out,
                       int H, int W) {
    __shared__ float sm[SW][SW];

    const int plane = blockIdx.z;
    const float* xp = x + (size_t)plane * H * W;
    float* op = out + (size_t)plane * H * W;
    const int x0 = blockIdx.x * TS;
    const int y0 = blockIdx.y * TS;
    const int tx = threadIdx.x;
    const int ty = threadIdx.y;
    const int tid = ty * 32 + tx;

    // ---- load 40x40 tile with reflect padding ----
    #pragma unroll
    for (int idx = tid; idx < SW * SW; idx += 256) {
        int ly = idx / SW, lx = idx - ly * SW;
        int gy = y0 + ly - HALO;
        int gx = x0 + lx - HALO;
        gy = gy < 0 ? -gy : (gy >= H ? 2 * H - 2 - gy : gy);
        gx = gx < 0 ? -gx : (gx >= W ? 2 * W - 2 - gx : gx);
        sm[ly][lx] = xp[(size_t)gy * W + gx];
    }
    __syncthreads();

    const float A = 1.0f / (2.0f * 1.7f * 1.7f);   // 0.1730104

    // exact 1D spatial gaussian (unnormalized): g[d] = exp(-A*d*d)
    float g[5];
    #pragma unroll
    for (int d = 0; d < 5; d++) g[d] = expf(-A * (float)(d * d));

    // degree-2 economized poly for exp(-A*u), u in [0,1]:
    //   Taylor-3 with u^3 ~ (48u^2 - 18u + 1)/32
    const float t1 = -A;
    const float t2 = 0.5f * A * A;
    const float t3 = -(A * A * A) * (1.0f / 6.0f);
    const float k2 = t2 + 1.5f * t3;
    const float k1 = t1 - 0.5625f * t3;
    const float k0 = 1.0f + t3 * (1.0f / 32.0f);

    // per-column coefficients with spatial weight folded in (5 distinct values,
    // CSE dedupes), broadcast into both f32x2 halves
    u64 K0[KS], K1[KS], K2[KS];
    #pragma unroll
    for (int j = 0; j < KS; j++) {
        float w = g[j < 4 ? 4 - j : j - 4];
        float a0 = w * k0, a1 = w * k1, a2 = w * k2;
        K0[j] = pack2(a0, a0);
        K1[j] = pack2(a1, a1);
        K2[j] = pack2(a2, a2);
    }

    float cv[PX];
    #pragma unroll
    for (int p = 0; p < PX; p++) cv[p] = sm[ty * PX + p + HALO][tx + HALO];
    const u64 nc01 = pack2(-cv[0], -cv[1]);
    const u64 nc23 = pack2(-cv[2], -cv[3]);

    u64 num01 = 0ull, den01 = 0ull, num23 = 0ull, den23 = 0ull;

    #pragma unroll
    for (int r = 0; r < PX + KS - 1; r++) {       // smem rows ty*PX + r
        const bool p01 = (r <= KS);               // pair (p0,p1) has a valid half
        const bool p23 = (r >= 2);                // pair (p2,p3) has a valid half
        u64 rn01 = 0ull, rd01 = 0ull, rn23 = 0ull, rd23 = 0ull;

        #pragma unroll
        for (int j = 0; j < KS; j++) {
            float v = sm[ty * PX + r][tx + j];
            u64 vv = pack2(v, v);
            if (p01) {
                u64 d = add2(vv, nc01);
                u64 u = mul2(d, d);
                u64 e = fma2(K2[j], u, K1[j]);
                e = fma2(e, u, K0[j]);
                rn01 = fma2(e, vv, rn01);
                rd01 = add2(rd01, e);
            }
            if (p23) {
                u64 d = add2(vv, nc23);
                u64 u = mul2(d, d);
                u64 e = fma2(K2[j], u, K1[j]);
                e = fma2(e, u, K0[j]);
                rn23 = fma2(e, vv, rn23);
                rd23 = add2(rd23, e);
            }
        }

        // row spatial weights; 0 kills the invalid (garbage-but-finite) half
        if (p01) {
            u64 gg = pack2(gw(g, r - 0), gw(g, r - 1));
            num01 = fma2(gg, rn01, num01);
            den01 = fma2(gg, rd01, den01);
        }
        if (p23) {
            u64 gg = pack2(gw(g, r - 2), gw(g, r - 3));
            num23 = fma2(gg, rn23, num23);
            den23 = fma2(gg, rd23, den23);
        }
    }

    float n0, n1, n2, n3, d0, d1, d2, d3;
    unpack2(num01, n0, n1); unpack2(den01, d0, d1);
    unpack2(num23, n2, n3); unpack2(den23, d2, d3);

    const int oy = y0 + ty * PX;
    op[(size_t)(oy + 0) * W + x0 + tx] = n0 / d0;
    op[(size_t)(oy + 1) * W + x0 + tx] = n1 / d1;
    op[(size_t)(oy + 2) * W + x0 + tx] = n2 / d2;
    op[(size_t)(oy + 3) * W + x0 + tx] = n3 / d3;
}

extern "C" void kernel_launch(void* const* d_in, const int* in_sizes, int n_in,
                              void* d_out, int out_size) {
    const float* x = (const float*)d_in[0];
    float* out = (float*)d_out;
    const int H = 384, W = 384;
    const int planes = out_size / (H * W);   // B*C = 6

    dim3 block(32, BY, 1);
    dim3 grid(W / TS, H / TS, planes);
    bilateral9_kernel<<<grid, block>>>(x, out, H, W);
}

// round 3
// speedup vs baseline: 2.1451x; 1.7187x over previous
#include <cuda_runtime.h>

// Bilateral filter, B=2 C=3 H=W=384, ksize=9, sigma=1.7.
// Density exp ~ degree-2 poly in u=(v-c)^2 => filter reduces to weighted
// spatial moments M_k = sum ws * v^k, k=1..5 (M0 = S^2 is constant), each a
// SEPARABLE 9-tap Gaussian convolution. Horizontal pass -> H1..H5 in smem,
// vertical pass + polynomial epilogue per pixel.
//
//   den = k2*M4 + q3*M3 + q2*M2 + q1*M1 + q0*S2
//   num = k2*M5 + q3*M4 + q2*M3 + q1*M2 + q0*M1
//   q3=-4*k2*c, q2=6*k2*c^2+k1, q1=-2c*(2*k2*c^2+k1), q0=k2*c^4+k1*c^2+k0

#define TS   32
#define BY   8
#define HALO 4
#define SW   40
#define KS   9

typedef unsigned long long u64;

__device__ __forceinline__ u64 pack2(float lo, float hi) {
    u64 r; asm("mov.b64 %0, {%1,%2};" : "=l"(r) : "f"(lo), "f"(hi)); return r;
}
__device__ __forceinline__ void unpack2(u64 v, float& lo, float& hi) {
    asm("mov.b64 {%0,%1}, %2;" : "=f"(lo), "=f"(hi) : "l"(v));
}
__device__ __forceinline__ u64 fma2(u64 a, u64 b, u64 c) {
    u64 d; asm("fma.rn.f32x2 %0, %1, %2, %3;" : "=l"(d) : "l"(a), "l"(b), "l"(c)); return d;
}
__device__ __forceinline__ u64 mul2(u64 a, u64 b) {
    u64 d; asm("mul.rn.f32x2 %0, %1, %2;" : "=l"(d) : "l"(a), "l"(b)); return d;
}

__global__ __launch_bounds__(256)
void bilateral9_kernel(const float* __restrict__ x, float* __restrict__ out,
                       int H, int W) {
    __shared__ float  raw[SW][SW];          // 6.4 KB
    __shared__ float4 h4[SW][TS];           // H1..H4, 20.5 KB
    __shared__ float  h5s[SW][TS];          // H5, 5.1 KB

    const int plane = blockIdx.z;
    const float* xp = x + (size_t)plane * H * W;
    float* op = out + (size_t)plane * H * W;
    const int x0 = blockIdx.x * TS;
    const int y0 = blockIdx.y * TS;
    const int tx = threadIdx.x;
    const int ty = threadIdx.y;
    const int tid = ty * 32 + tx;

    // ---- load 40x40 raw tile with reflect padding ----
    #pragma unroll
    for (int idx = tid; idx < SW * SW; idx += 256) {
        int ly = idx / SW, lx = idx - ly * SW;
        int gy = y0 + ly - HALO;
        int gx = x0 + lx - HALO;
        gy = gy < 0 ? -gy : (gy >= H ? 2 * H - 2 - gy : gy);
        gx = gx < 0 ? -gx : (gx >= W ? 2 * W - 2 - gx : gx);
        raw[ly][lx] = xp[(size_t)gy * W + gx];
    }

    const float A = 1.0f / (2.0f * 1.7f * 1.7f);   // 0.1730104

    float g[5];
    #pragma unroll
    for (int d = 0; d < 5; d++) g[d] = expf(-A * (float)(d * d));
    const float S  = g[0] + 2.0f * (g[1] + g[2] + g[3] + g[4]);
    const float S2 = S * S;

    // degree-2 economized poly for exp(-A*u), u in [0,1]
    const float t1 = -A;
    const float t2 = 0.5f * A * A;
    const float t3 = -(A * A * A) * (1.0f / 6.0f);
    const float k2 = t2 + 1.5f * t3;
    const float k1 = t1 - 0.5625f * t3;
    const float k0 = 1.0f + t3 * (1.0f / 32.0f);

    __syncthreads();

    // ---- horizontal pass: H_k(row, col) = sum_j g|j-4| * raw[row][col+j]^k
    // 40 rows x 32 cols; thread handles rows {ty, ty+8, 16+ty, 24+ty, 32+ty}
    // at col tx. Row-pairs packed in f32x2.
    #pragma unroll
    for (int mp = 0; mp < 2; mp++) {
        const int ra = mp * 16 + ty;
        const int rb = ra + 8;
        u64 a1 = 0ull, a2 = 0ull, a3 = 0ull, a4 = 0ull, a5 = 0ull;
        #pragma unroll
        for (int j = 0; j < KS; j++) {
            u64 vv = pack2(raw[ra][tx + j], raw[rb][tx + j]);
            u64 v2 = mul2(vv, vv);
            u64 v3 = mul2(v2, vv);
            u64 v4 = mul2(v2, v2);
            u64 v5 = mul2(v4, vv);
            float w = g[j < 4 ? 4 - j : j - 4];
            u64 gg = pack2(w, w);
            a1 = fma2(gg, vv, a1);
            a2 = fma2(gg, v2, a2);
            a3 = fma2(gg, v3, a3);
            a4 = fma2(gg, v4, a4);
            a5 = fma2(gg, v5, a5);
        }
        float f1a, f1b, f2a, f2b, f3a, f3b, f4a, f4b, f5a, f5b;
        unpack2(a1, f1a, f1b); unpack2(a2, f2a, f2b);
        unpack2(a3, f3a, f3b); unpack2(a4, f4a, f4b);
        unpack2(a5, f5a, f5b);
        h4[ra][tx] = make_float4(f1a, f2a, f3a, f4a);
        h4[rb][tx] = make_float4(f1b, f2b, f3b, f4b);
        h5s[ra][tx] = f5a;
        h5s[rb][tx] = f5b;
    }
    {   // last row (32+ty), scalar
        const int r = 32 + ty;
        float a1 = 0.f, a2 = 0.f, a3 = 0.f, a4 = 0.f, a5 = 0.f;
        #pragma unroll
        for (int j = 0; j < KS; j++) {
            float v = raw[r][tx + j];
            float v2 = v * v, v3 = v2 * v, v4 = v2 * v2, v5 = v4 * v;
            float w = g[j < 4 ? 4 - j : j - 4];
            a1 = fmaf(w, v, a1);
            a2 = fmaf(w, v2, a2);
            a3 = fmaf(w, v3, a3);
            a4 = fmaf(w, v4, a4);
            a5 = fmaf(w, v5, a5);
        }
        h4[r][tx] = make_float4(a1, a2, a3, a4);
        h5s[r][tx] = a5;
    }
    __syncthreads();

    // ---- vertical pass + epilogue: 4 pixels per thread (rows 4*ty..4*ty+3)
    u64 m12[4], m34[4];
    float m5[4];
    #pragma unroll
    for (int p = 0; p < 4; p++) { m12[p] = 0ull; m34[p] = 0ull; m5[p] = 0.f; }

    #pragma unroll
    for (int r = 0; r < 12; r++) {
        float4 h = h4[ty * 4 + r][tx];
        float hv5 = h5s[ty * 4 + r][tx];
        u64 h12 = pack2(h.x, h.y);
        u64 h34 = pack2(h.z, h.w);
        #pragma unroll
        for (int p = 0; p < 4; p++) {
            const int t = r - p;
            if (t >= 0 && t < KS) {                 // compile-time pruned
                float gy = g[t < 4 ? 4 - t : t - 4];
                u64 gg = pack2(gy, gy);
                m12[p] = fma2(gg, h12, m12[p]);
                m34[p] = fma2(gg, h34, m34[p]);
                m5[p]  = fmaf(gy, hv5, m5[p]);
            }
        }
    }

    const float n4k2 = -4.0f * k2;
    const float s6k2 = 6.0f * k2;
    const float s2k2 = 2.0f * k2;

    #pragma unroll
    for (int p = 0; p < 4; p++) {
        float M1, M2, M3, M4;
        unpack2(m12[p], M1, M2);
        unpack2(m34[p], M3, M4);
        float M5 = m5[p];

        float c = raw[ty * 4 + p + HALO][tx + HALO];
        float c2 = c * c;
        float c4 = c2 * c2;
        float q3 = n4k2 * c;
        float q2 = fmaf(s6k2, c2, k1);
        float tq = fmaf(s2k2, c2, k1);
        float q1 = -2.0f * c * tq;
        float q0 = fmaf(k2, c4, fmaf(k1, c2, k0));

        float den = fmaf(q3, M3, k2 * M4);
        den = fmaf(q2, M2, den);
        den = fmaf(q1, M1, den);
        den = fmaf(q0, S2, den);

        float num = fmaf(q3, M4, k2 * M5);
        num = fmaf(q2, M3, num);
        num = fmaf(q1, M2, num);
        num = fmaf(q0, M1, num);

        int oy = y0 + ty * 4 + p;
        op[(size_t)oy * W + x0 + tx] = __fdividef(num, den);
    }
}

extern "C" void kernel_launch(void* const* d_in, const int* in_sizes, int n_in,
                              void* d_out, int out_size) {
    const float* x = (const float*)d_in[0];
    float* out = (float*)d_out;
    const int H = 384, W = 384;
    const int planes = out_size / (H * W);   // B*C = 6

    dim3 block(32, BY, 1);
    dim3 grid(W / TS, H / TS, planes);
    bilateral9_kernel<<<grid, block>>>(x, out, H, W);
}

// round 4
// speedup vs baseline: 2.3670x; 1.1034x over previous
#include <cuda_runtime.h>

// Bilateral filter, B=2 C=3 H=W=384, ksize=9, sigma=1.7.
// Moments M_k = separable 9-tap Gaussian of v^k (k=1..5); density exp is a
// degree-2 poly in u=(v-c)^2. All constants compile-time. Horizontal pass is
// column-pair packed (f32x2) with aligned LDS.64 window loads.

#define TS   32
#define HALO 4
#define SW   40
#define KS   9

typedef unsigned long long u64;

// exp(-A*d*d), A = 1/(2*1.7^2) = 0.17301038062...
#define G0f 1.00000000f
#define G1f 0.84112888f
#define G2f 0.50055313f
#define G3f 0.21074770f
#define G4f 0.06277701f
#define S2f 17.8963970f
// degree-2 economized poly for exp(-A*u) on u in [0,1]
#define K2f 0.013671630f
#define K1f (-0.17252488f)
#define K0f 0.99997303f

__device__ __forceinline__ u64 pack2(float lo, float hi) {
    u64 r; asm("mov.b64 %0, {%1,%2};" : "=l"(r) : "f"(lo), "f"(hi)); return r;
}
__device__ __forceinline__ void unpack2(u64 v, float& lo, float& hi) {
    asm("mov.b64 {%0,%1}, %2;" : "=f"(lo), "=f"(hi) : "l"(v));
}
__device__ __forceinline__ u64 fma2(u64 a, u64 b, u64 c) {
    u64 d; asm("fma.rn.f32x2 %0, %1, %2, %3;" : "=l"(d) : "l"(a), "l"(b), "l"(c)); return d;
}
__device__ __forceinline__ u64 mul2(u64 a, u64 b) {
    u64 d; asm("mul.rn.f32x2 %0, %1, %2;" : "=l"(d) : "l"(a), "l"(b)); return d;
}

__global__ __launch_bounds__(256, 6)
void bilateral9_kernel(const float* __restrict__ x, float* __restrict__ out,
                       int H, int W) {
    __shared__ __align__(16) float raw[SW][SW];   // 6.4 KB
    __shared__ float4 h4[SW][TS];                 // 20.5 KB
    __shared__ float  h5s[SW][TS];                // 5.1 KB

    const int plane = blockIdx.z;
    const float* xp = x + (size_t)plane * H * W;
    float* op = out + (size_t)plane * H * W;
    const int x0 = blockIdx.x * TS;
    const int y0 = blockIdx.y * TS;
    const int tid = threadIdx.x;

    // ---- load 40x40 raw tile ----
    const bool interior = (x0 >= HALO) && (x0 + TS + HALO <= W) &&
                          (y0 >= HALO) && (y0 + TS + HALO <= H);
    if (interior) {
        const float* src = xp + (size_t)(y0 - HALO) * W + (x0 - HALO);
        #pragma unroll
        for (int k = 0; k < 4; k++) {
            int idx = tid + k * 256;
            if (idx < 800) {                  // 800 float2 = 1600 floats
                int ly = idx / 20;
                int lx = idx - ly * 20;
                float2 v = *(const float2*)(src + (size_t)ly * W + lx * 2);
                *(float2*)&raw[ly][lx * 2] = v;
            }
        }
    } else {
        #pragma unroll
        for (int k = 0; k < 7; k++) {
            int idx = tid + k * 256;
            if (idx < 1600) {
                int ly = idx / 40;
                int lx = idx - ly * 40;
                int gy = y0 + ly - HALO;
                int gx = x0 + lx - HALO;
                gy = gy < 0 ? -gy : (gy >= H ? 2 * H - 2 - gy : gy);
                gx = gx < 0 ? -gx : (gx >= W ? 2 * W - 2 - gx : gx);
                raw[ly][lx] = xp[(size_t)gy * W + gx];
            }
        }
    }
    __syncthreads();

    const u64 GG[5] = { pack2(G0f, G0f), pack2(G1f, G1f), pack2(G2f, G2f),
                        pack2(G3f, G3f), pack2(G4f, G4f) };

    // ---- horizontal pass: col-pair packed. 40 rows x 16 col-pairs ----
    {
        const int cp  = tid & 15;        // col-pair 0..15 -> cols 2cp, 2cp+1
        const int rid = tid >> 4;        // 0..15
        #pragma unroll
        for (int rr = 0; rr < 3; rr++) {
            const int r = rid + rr * 16;
            if (rr < 2 || rid < 8) {     // rows 0..39
                const float* rp = &raw[r][2 * cp];
                float2 L0 = *(const float2*)(rp + 0);
                float2 L1 = *(const float2*)(rp + 2);
                float2 L2 = *(const float2*)(rp + 4);
                float2 L3 = *(const float2*)(rp + 6);
                float2 L4 = *(const float2*)(rp + 8);
                u64 V[9];
                V[0] = pack2(L0.x, L0.y);
                V[1] = pack2(L0.y, L1.x);
                V[2] = pack2(L1.x, L1.y);
                V[3] = pack2(L1.y, L2.x);
                V[4] = pack2(L2.x, L2.y);
                V[5] = pack2(L2.y, L3.x);
                V[6] = pack2(L3.x, L3.y);
                V[7] = pack2(L3.y, L4.x);
                V[8] = pack2(L4.x, L4.y);

                u64 a1, a2, a3, a4, a5;
                {   // j = 0, weight g4 (init via mul)
                    u64 vv = V[0];
                    u64 v2 = mul2(vv, vv), v3 = mul2(v2, vv);
                    u64 v4 = mul2(v2, v2), v5 = mul2(v4, vv);
                    a1 = mul2(GG[4], vv); a2 = mul2(GG[4], v2);
                    a3 = mul2(GG[4], v3); a4 = mul2(GG[4], v4);
                    a5 = mul2(GG[4], v5);
                }
                #pragma unroll
                for (int j = 1; j < KS; j++) {
                    u64 vv = V[j];
                    u64 v2 = mul2(vv, vv), v3 = mul2(v2, vv);
                    u64 v4 = mul2(v2, v2), v5 = mul2(v4, vv);
                    const u64 g = GG[j < 4 ? 4 - j : j - 4];
                    a1 = fma2(g, vv, a1); a2 = fma2(g, v2, a2);
                    a3 = fma2(g, v3, a3); a4 = fma2(g, v4, a4);
                    a5 = fma2(g, v5, a5);
                }

                float u1, w1, u2, w2, u3, w3, u4, w4, u5, w5;
                unpack2(a1, u1, w1); unpack2(a2, u2, w2);
                unpack2(a3, u3, w3); unpack2(a4, u4, w4);
                unpack2(a5, u5, w5);
                h4[r][2 * cp]     = make_float4(u1, u2, u3, u4);
                h4[r][2 * cp + 1] = make_float4(w1, w2, w3, w4);
                h5s[r][2 * cp]     = u5;
                h5s[r][2 * cp + 1] = w5;
            }
        }
    }
    __syncthreads();

    // ---- vertical pass: 4 pixels per thread, moments packed (M1,M2)/(M3,M4)
    const int tx = tid & 31;
    const int ty = tid >> 5;

    u64 m12[4], m34[4];
    float m5v[4];
    #pragma unroll
    for (int p = 0; p < 4; p++) { m12[p] = 0ull; m34[p] = 0ull; m5v[p] = 0.0f; }

    const float Gs[5] = { G0f, G1f, G2f, G3f, G4f };

    #pragma unroll
    for (int r = 0; r < 12; r++) {
        float4 h = h4[ty * 4 + r][tx];
        float hv5 = h5s[ty * 4 + r][tx];
        u64 h12 = pack2(h.x, h.y);
        u64 h34 = pack2(h.z, h.w);
        #pragma unroll
        for (int p = 0; p < 4; p++) {
            const int t = r - p;
            if (t >= 0 && t < KS) {                 // compile-time pruned
                const int d = t < 4 ? 4 - t : t - 4;
                m12[p] = fma2(GG[d], h12, m12[p]);
                m34[p] = fma2(GG[d], h34, m34[p]);
                m5v[p] = fmaf(Gs[d], hv5, m5v[p]);
            }
        }
    }

    // ---- epilogue ----
    #pragma unroll
    for (int p = 0; p < 4; p++) {
        float M1, M2, M3, M4;
        unpack2(m12[p], M1, M2);
        unpack2(m34[p], M3, M4);
        float M5 = m5v[p];

        float c  = raw[ty * 4 + p + HALO][tx + HALO];
        float c2 = c * c;
        float c4 = c2 * c2;
        float q3 = (-4.0f * K2f) * c;
        float q2 = fmaf(6.0f * K2f, c2, K1f);
        float tq = fmaf(2.0f * K2f, c2, K1f);
        float q1 = -2.0f * c * tq;
        float q0 = fmaf(K2f, c4, fmaf(K1f, c2, K0f));

        float den = fmaf(q3, M3, K2f * M4);
        den = fmaf(q2, M2, den);
        den = fmaf(q1, M1, den);
        den = fmaf(q0, S2f, den);

        float num = fmaf(q3, M4, K2f * M5);
        num = fmaf(q2, M3, num);
        num = fmaf(q1, M2, num);
        num = fmaf(q0, M1, num);

        int oy = y0 + ty * 4 + p;
        op[(size_t)oy * W + x0 + tx] = __fdividef(num, den);
    }
}

extern "C" void kernel_launch(void* const* d_in, const int* in_sizes, int n_in,
                              void* d_out, int out_size) {
    const float* x = (const float*)d_in[0];
    float* out = (float*)d_out;
    const int H = 384, W = 384;
    const int planes = out_size / (H * W);   // B*C = 6

    dim3 block(256, 1, 1);
    dim3 grid(W / TS, H / TS, planes);
    bilateral9_kernel<<<grid, block>>>(x, out, H, W);
}

// round 5
// speedup vs baseline: 2.9121x; 1.2303x over previous
#include <cuda_runtime.h>

// Bilateral filter, B=2 C=3 H=W=384, ksize=9, sigma=1.7.
// Density exp ~ minimax LINEAR poly in u=(v-c)^2 on [0,1] (weight err 1.7e-3
// -> output err ~1e-4, gate 1e-3). Filter reduces to separable 9-tap Gaussian
// moments M1,M2,M3:
//   den = b1*M2 + (-2*b1*c)*M1 + (b0+b1*c^2)*S2
//   num = b1*M3 + (-2*b1*c)*M2 + (b0+b1*c^2)*M1

#define TS   32
#define HALO 4
#define SW   40
#define KS   9

typedef unsigned long long u64;

// exp(-A*d*d), A = 1/(2*1.7^2)
#define G0f 1.00000000f
#define G1f 0.84112888f
#define G2f 0.50055313f
#define G3f 0.21074770f
#define G4f 0.06277701f
#define S2f 17.8963970f
// minimax linear for exp(-A*u), u in [0,1]
#define B0f 0.99828148f
#define B1f (-0.15887112f)

__device__ __forceinline__ u64 pack2(float lo, float hi) {
    u64 r; asm("mov.b64 %0, {%1,%2};" : "=l"(r) : "f"(lo), "f"(hi)); return r;
}
__device__ __forceinline__ void unpack2(u64 v, float& lo, float& hi) {
    asm("mov.b64 {%0,%1}, %2;" : "=f"(lo), "=f"(hi) : "l"(v));
}
__device__ __forceinline__ u64 fma2(u64 a, u64 b, u64 c) {
    u64 d; asm("fma.rn.f32x2 %0, %1, %2, %3;" : "=l"(d) : "l"(a), "l"(b), "l"(c)); return d;
}
__device__ __forceinline__ u64 mul2(u64 a, u64 b) {
    u64 d; asm("mul.rn.f32x2 %0, %1, %2;" : "=l"(d) : "l"(a), "l"(b)); return d;
}

__global__ __launch_bounds__(256, 6)
void bilateral9_kernel(const float* __restrict__ x, float* __restrict__ out,
                       int H, int W) {
    __shared__ __align__(16) float raw[SW][SW];   // 6.4 KB
    __shared__ float2 h12[SW][TS];                // (M1,M2) 10.25 KB
    __shared__ float  h3s[SW][TS];                // M3 5.1 KB

    const int plane = blockIdx.z;
    const float* xp = x + (size_t)plane * H * W;
    float* op = out + (size_t)plane * H * W;
    const int x0 = blockIdx.x * TS;
    const int y0 = blockIdx.y * TS;
    const int tid = threadIdx.x;

    // ---- load 40x40 raw tile ----
    const bool interior = (x0 >= HALO) && (x0 + TS + HALO <= W) &&
                          (y0 >= HALO) && (y0 + TS + HALO <= H);
    if (interior) {
        const float* src = xp + (size_t)(y0 - HALO) * W + (x0 - HALO);
        #pragma unroll
        for (int k = 0; k < 4; k++) {
            int idx = tid + k * 256;
            if (idx < 800) {
                int ly = idx / 20;
                int lx = idx - ly * 20;
                float2 v = *(const float2*)(src + (size_t)ly * W + lx * 2);
                *(float2*)&raw[ly][lx * 2] = v;
            }
        }
    } else {
        #pragma unroll
        for (int k = 0; k < 7; k++) {
            int idx = tid + k * 256;
            if (idx < 1600) {
                int ly = idx / 40;
                int lx = idx - ly * 40;
                int gy = y0 + ly - HALO;
                int gx = x0 + lx - HALO;
                gy = gy < 0 ? -gy : (gy >= H ? 2 * H - 2 - gy : gy);
                gx = gx < 0 ? -gx : (gx >= W ? 2 * W - 2 - gx : gx);
                raw[ly][lx] = xp[(size_t)gy * W + gx];
            }
        }
    }
    __syncthreads();

    const u64 GG[5] = { pack2(G0f, G0f), pack2(G1f, G1f), pack2(G2f, G2f),
                        pack2(G3f, G3f), pack2(G4f, G4f) };

    // ---- horizontal pass: col-pair packed, moments M1..M3 ----
    {
        const int cp  = tid & 15;        // cols 2cp, 2cp+1
        const int rid = tid >> 4;        // 0..15
        #pragma unroll
        for (int rr = 0; rr < 3; rr++) {
            const int r = rid + rr * 16;
            if (rr < 2 || rid < 8) {     // rows 0..39
                const float* rp = &raw[r][2 * cp];
                float2 L0 = *(const float2*)(rp + 0);
                float2 L1 = *(const float2*)(rp + 2);
                float2 L2 = *(const float2*)(rp + 4);
                float2 L3 = *(const float2*)(rp + 6);
                float2 L4 = *(const float2*)(rp + 8);
                u64 V[9];
                V[0] = pack2(L0.x, L0.y);
                V[1] = pack2(L0.y, L1.x);
                V[2] = pack2(L1.x, L1.y);
                V[3] = pack2(L1.y, L2.x);
                V[4] = pack2(L2.x, L2.y);
                V[5] = pack2(L2.y, L3.x);
                V[6] = pack2(L3.x, L3.y);
                V[7] = pack2(L3.y, L4.x);
                V[8] = pack2(L4.x, L4.y);

                u64 a1, a2, a3;
                {   // j = 0, weight g4
                    u64 vv = V[0];
                    u64 v2 = mul2(vv, vv), v3 = mul2(v2, vv);
                    a1 = mul2(GG[4], vv);
                    a2 = mul2(GG[4], v2);
                    a3 = mul2(GG[4], v3);
                }
                #pragma unroll
                for (int j = 1; j < KS; j++) {
                    u64 vv = V[j];
                    u64 v2 = mul2(vv, vv), v3 = mul2(v2, vv);
                    const u64 g = GG[j < 4 ? 4 - j : j - 4];
                    a1 = fma2(g, vv, a1);
                    a2 = fma2(g, v2, a2);
                    a3 = fma2(g, v3, a3);
                }

                float u1, w1, u2, w2, u3, w3;
                unpack2(a1, u1, w1);
                unpack2(a2, u2, w2);
                unpack2(a3, u3, w3);
                h12[r][2 * cp]     = make_float2(u1, u2);
                h12[r][2 * cp + 1] = make_float2(w1, w2);
                h3s[r][2 * cp]     = u3;
                h3s[r][2 * cp + 1] = w3;
            }
        }
    }
    __syncthreads();

    // ---- vertical pass: 4 pixels per thread, (M1,M2) packed + M3 scalar ----
    const int tx = tid & 31;
    const int ty = tid >> 5;

    u64 m12[4];
    float m3v[4];
    #pragma unroll
    for (int p = 0; p < 4; p++) { m12[p] = 0ull; m3v[p] = 0.0f; }

    const float Gs[5] = { G0f, G1f, G2f, G3f, G4f };

    #pragma unroll
    for (int r = 0; r < 12; r++) {
        float2 h = h12[ty * 4 + r][tx];
        float hv3 = h3s[ty * 4 + r][tx];
        u64 hp = pack2(h.x, h.y);
        #pragma unroll
        for (int p = 0; p < 4; p++) {
            const int t = r - p;
            if (t >= 0 && t < KS) {                 // compile-time pruned
                const int d = t < 4 ? 4 - t : t - 4;
                m12[p] = fma2(GG[d], hp, m12[p]);
                m3v[p] = fmaf(Gs[d], hv3, m3v[p]);  // imm-weight FFMA
            }
        }
    }

    // ---- epilogue ----
    #pragma unroll
    for (int p = 0; p < 4; p++) {
        float M1, M2;
        unpack2(m12[p], M1, M2);
        float M3 = m3v[p];

        float c  = raw[ty * 4 + p + HALO][tx + HALO];
        float c2 = c * c;
        float p1 = (-2.0f * B1f) * c;              // -2*b1*c
        float q  = fmaf(B1f, c2, B0f);             // b0 + b1*c^2

        float den = fmaf(q, S2f, fmaf(p1, M1, B1f * M2));
        float num = fmaf(q, M1,  fmaf(p1, M2, B1f * M3));

        int oy = y0 + ty * 4 + p;
        op[(size_t)oy * W + x0 + tx] = __fdividef(num, den);
    }
}

extern "C" void kernel_launch(void* const* d_in, const int* in_sizes, int n_in,
                              void* d_out, int out_size) {
    const float* x = (const float*)d_in[0];
    float* out = (float*)d_out;
    const int H = 384, W = 384;
    const int planes = out_size / (H * W);   // B*C = 6

    dim3 block(256, 1, 1);
    dim3 grid(W / TS, H / TS, planes);
    bilateral9_kernel<<<grid, block>>>(x, out, H, W);
}

// round 7
// speedup vs baseline: 2.9938x; 1.0280x over previous
#include <cuda_runtime.h>

// Bilateral filter, B=2 C=3 H=W=384, ksize=9, sigma=1.7.
// Density exp ~ minimax linear poly in u=(v-c)^2 on [0,1]; filter = separable
// 9-tap Gaussian moments M1,M2,M3:
//   den = b1*M2 + (-2*b1*c)*M1 + (b0+b1*c^2)*S2
//   num = b1*M3 + (-2*b1*c)*M2 + (b0+b1*c^2)*M1
// Tile 64x32 out, 72x40 halo, 256 threads, 3 CTAs/SM, single wave (432 CTAs).

#define TW   64          // tile width (out)
#define TH   32          // tile height (out)
#define HALO 4
#define SWX  72          // raw cols
#define SWXP 76          // raw row stride (16B-aligned)
#define SWY  40          // raw rows
#define KS   9

typedef unsigned long long u64;

// exp(-A*d*d), A = 1/(2*1.7^2)
#define G0f 1.00000000f
#define G1f 0.84112888f
#define G2f 0.50055313f
#define G3f 0.21074770f
#define G4f 0.06277701f
#define S2f 17.8963970f
// minimax linear for exp(-A*u), u in [0,1]
#define B0f 0.99828148f
#define B1f (-0.15887112f)

__device__ __forceinline__ u64 pack2(float lo, float hi) {
    u64 r; asm("mov.b64 %0, {%1,%2};" : "=l"(r) : "f"(lo), "f"(hi)); return r;
}
__device__ __forceinline__ void unpack2(u64 v, float& lo, float& hi) {
    asm("mov.b64 {%0,%1}, %2;" : "=f"(lo), "=f"(hi) : "l"(v));
}
__device__ __forceinline__ u64 fma2(u64 a, u64 b, u64 c) {
    u64 d; asm("fma.rn.f32x2 %0, %1, %2, %3;" : "=l"(d) : "l"(a), "l"(b), "l"(c)); return d;
}
__device__ __forceinline__ u64 mul2(u64 a, u64 b) {
    u64 d; asm("mul.rn.f32x2 %0, %1, %2;" : "=l"(d) : "l"(a), "l"(b)); return d;
}

__global__ __launch_bounds__(256, 3)
void bilateral9_kernel(const float* __restrict__ x, float* __restrict__ out,
                       int H, int W) {
    __shared__ __align__(16) float raw[SWY][SWXP];   // 11.9 KB
    __shared__ float2 h12[SWY][TW];                  // 20.0 KB
    __shared__ float  h3s[SWY][TW];                  // 10.0 KB

    const int plane = blockIdx.z;
    const float* xp = x + (size_t)plane * H * W;
    float* op = out + (size_t)plane * H * W;
    const int x0 = blockIdx.x * TW;
    const int y0 = blockIdx.y * TH;
    const int tid = threadIdx.x;

    // ---- load 72x40 raw tile ----
    const bool interior = (x0 >= HALO) && (x0 + TW + HALO <= W) &&
                          (y0 >= HALO) && (y0 + TH + HALO <= H);
    if (interior) {
        const float* src = xp + (size_t)(y0 - HALO) * W + (x0 - HALO);
        #pragma unroll
        for (int k = 0; k < 3; k++) {
            int idx = tid + k * 256;                 // 720 float4 = 2880 floats
            if (idx < 720) {
                int ly = idx / 18;                   // 18 float4 per row
                int lx = idx - ly * 18;
                float4 v = *(const float4*)(src + (size_t)ly * W + lx * 4);
                *(float4*)&raw[ly][lx * 4] = v;
            }
        }
    } else {
        #pragma unroll
        for (int k = 0; k < 12; k++) {
            int idx = tid + k * 256;
            if (idx < 2880) {
                int ly = idx / SWX;
                int lx = idx - ly * SWX;
                int gy = y0 + ly - HALO;
                int gx = x0 + lx - HALO;
                gy = gy < 0 ? -gy : (gy >= H ? 2 * H - 2 - gy : gy);
                gx = gx < 0 ? -gx : (gx >= W ? 2 * W - 2 - gx : gx);
                raw[ly][lx] = xp[(size_t)gy * W + gx];
            }
        }
    }
    __syncthreads();

    const u64 GG[5] = { pack2(G0f, G0f), pack2(G1f, G1f), pack2(G2f, G2f),
                        pack2(G3f, G3f), pack2(G4f, G4f) };

    // ---- horizontal pass: col-pair packed, moments M1..M3 ----
    // 40 rows x 32 col-pairs = 1280 units = 5 per thread (rows rid+{0,8,..,32})
    {
        const int cp  = tid & 31;        // cols 2cp, 2cp+1
        const int rid = tid >> 5;        // 0..7
        #pragma unroll
        for (int rr = 0; rr < 5; rr++) {
            const int r = rid + rr * 8;
            const float* rp = &raw[r][2 * cp];
            float2 L0 = *(const float2*)(rp + 0);
            float2 L1 = *(const float2*)(rp + 2);
            float2 L2 = *(const float2*)(rp + 4);
            float2 L3 = *(const float2*)(rp + 6);
            float2 L4 = *(const float2*)(rp + 8);
            u64 V[9];
            V[0] = pack2(L0.x, L0.y);
            V[1] = pack2(L0.y, L1.x);
            V[2] = pack2(L1.x, L1.y);
            V[3] = pack2(L1.y, L2.x);
            V[4] = pack2(L2.x, L2.y);
            V[5] = pack2(L2.y, L3.x);
            V[6] = pack2(L3.x, L3.y);
            V[7] = pack2(L3.y, L4.x);
            V[8] = pack2(L4.x, L4.y);

            u64 a1, a2, a3;
            {   // j = 0, weight g4
                u64 vv = V[0];
                u64 v2 = mul2(vv, vv), v3 = mul2(v2, vv);
                a1 = mul2(GG[4], vv);
                a2 = mul2(GG[4], v2);
                a3 = mul2(GG[4], v3);
            }
            #pragma unroll
            for (int j = 1; j < KS; j++) {
                u64 vv = V[j];
                u64 v2 = mul2(vv, vv), v3 = mul2(v2, vv);
                const u64 g = GG[j < 4 ? 4 - j : j - 4];
                a1 = fma2(g, vv, a1);
                a2 = fma2(g, v2, a2);
                a3 = fma2(g, v3, a3);
            }

            float u1, w1, u2, w2, u3, w3;
            unpack2(a1, u1, w1);
            unpack2(a2, u2, w2);
            unpack2(a3, u3, w3);
            h12[r][2 * cp]     = make_float2(u1, u2);
            h12[r][2 * cp + 1] = make_float2(w1, w2);
            h3s[r][2 * cp]     = u3;
            h3s[r][2 * cp + 1] = w3;
        }
    }
    __syncthreads();

    // ---- vertical pass: 8 pixels per thread (rows 8*tyg .. 8*tyg+7) ----
    const int tx  = tid & 63;
    const int tyg = tid >> 6;            // 0..3

    u64 m12[8];
    float m3v[8];
    #pragma unroll
    for (int p = 0; p < 8; p++) { m12[p] = 0ull; m3v[p] = 0.0f; }

    const float Gs[5] = { G0f, G1f, G2f, G3f, G4f };

    #pragma unroll
    for (int r = 0; r < 16; r++) {
        float2 h = h12[tyg * 8 + r][tx];
        float hv3 = h3s[tyg * 8 + r][tx];
        u64 hp = pack2(h.x, h.y);
        #pragma unroll
        for (int p = 0; p < 8; p++) {
            const int t = r - p;
            if (t >= 0 && t < KS) {                 // compile-time pruned
                const int d = t < 4 ? 4 - t : t - 4;
                m12[p] = fma2(GG[d], hp, m12[p]);
                m3v[p] = fmaf(Gs[d], hv3, m3v[p]);  // imm-weight FFMA
            }
        }
    }

    // ---- epilogue ----
    #pragma unroll
    for (int p = 0; p < 8; p++) {
        float M1, M2;
        unpack2(m12[p], M1, M2);
        float M3 = m3v[p];

        float c  = raw[tyg * 8 + p + HALO][tx + HALO];
        float c2 = c * c;
        float p1 = (-2.0f * B1f) * c;              // -2*b1*c
        float q  = fmaf(B1f, c2, B0f);             // b0 + b1*c^2

        float den = fmaf(q, S2f, fmaf(p1, M1, B1f * M2));
        float num = fmaf(q, M1,  fmaf(p1, M2, B1f * M3));

        int oy = y0 + tyg * 8 + p;
        op[(size_t)oy * W + x0 + tx] = __fdividef(num, den);
    }
}

extern "C" void kernel_launch(void* const* d_in, const int* in_sizes, int n_in,
                              void* d_out, int out_size) {
    const float* x = (const float*)d_in[0];
    float* out = (float*)d_out;
    const int H = 384, W = 384;
    const int planes = out_size / (H * W);   // B*C = 6

    dim3 block(256, 1, 1);
    dim3 grid(W / TW, H / TH, planes);
    bilateral9_kernel<<<grid, block>>>(x, out, H, W);
}